// round 11
// baseline (speedup 1.0000x reference)
#include <cuda_runtime.h>

#define NB 256
#define NH 500
#define NI 784
#define NO 10
#define TT 200

#define V0F  2.1165347359575993f   // f32(eta^(eta/(eta-1))/(eta-1)), eta=4
#define SIGF 0.7788007830714049f   // f32(exp(-1/4))

typedef unsigned long long u64;

// static device scratch (allowed per harness rules)
__device__ float d_ann[NB*NH];
__device__ float d_cur[TT*NB*NH];        // 102.4 MB (cur2, reused for cur3)
__device__ float d_w2[TT*NB*NH];         // 102.4 MB
__device__ float d_w3[TT*NB*NO];         // 2 MB

__device__ __forceinline__ void ffma2(u64 &acc, u64 a, u64 b) {
    asm("fma.rn.f32x2 %0, %1, %2, %0;" : "+l"(acc) : "l"(a), "l"(b));
}
__device__ __forceinline__ float2 unpack2(u64 v) {
    float2 f; asm("mov.b64 {%0,%1}, %2;" : "=f"(f.x), "=f"(f.y) : "l"(v));
    return f;
}
__device__ __forceinline__ u64 dup2(float v) {
    u64 d; asm("mov.b64 %0, {%1, %1};" : "=l"(d) : "f"(v)); return d;
}

// XLA f32 tanh (rational approx, strict unfused) + logistic expansion
__device__ __forceinline__ float xla_tanh(float x) {
    const float xc = fminf(fmaxf(x, -7.90531110763549805f), 7.90531110763549805f);
    const float x2 = __fmul_rn(xc, xc);
    float p = -2.76076847742355e-16f;
    p = __fadd_rn(__fmul_rn(p, x2),  2.00018790482477e-13f);
    p = __fadd_rn(__fmul_rn(p, x2), -8.60467152213735e-11f);
    p = __fadd_rn(__fmul_rn(p, x2),  5.12229709037114e-08f);
    p = __fadd_rn(__fmul_rn(p, x2),  1.48572235717979e-05f);
    p = __fadd_rn(__fmul_rn(p, x2),  6.37261928875436e-04f);
    p = __fadd_rn(__fmul_rn(p, x2),  4.89352455891786e-03f);
    const float num = __fmul_rn(xc, p);
    float q = 1.19825839466702e-06f;
    q = __fadd_rn(__fmul_rn(q, x2), 1.18534705686654e-04f);
    q = __fadd_rn(__fmul_rn(q, x2), 2.26843463243900e-03f);
    q = __fadd_rn(__fmul_rn(q, x2), 4.89352518554385e-03f);
    const float t = __fdiv_rn(num, q);
    return (fabsf(x) < 0.0004f) ? x : t;
}
__device__ __forceinline__ float xla_logistic(float z) {
    return __fadd_rn(0.5f, __fmul_rn(0.5f, xla_tanh(__fmul_rn(0.5f, z))));
}

// ---------------------------------------------------------------------------
// Strict GEMM v7: C[m,n] = epi(chain_k fma(A[m,k],B[n,k]) + bias[n])
// Tile 256m x 128n x 8k, 256 threads, double-buffered, 1 CTA/SM.
// Thread tile 8m x 16n (64 u64 accs). 1.0 smem-byte/FMA: A dup-pairs (v5
// layout, 20-float-strided chunks), B natural (n,n+1) pairs in 20-float-
// strided chunks; all compute LDS.128 bank-conflict-free.
// Per output: single accumulator, strictly k-ascending fma.rn chain.
// Requires: M % 256 == 0, K % 4 == 0.
// ---------------------------------------------------------------------------
__global__ void __launch_bounds__(256, 1) gemm_strict_v7(
    const float* __restrict__ A, const float* __restrict__ B,
    const float* __restrict__ bias, float* __restrict__ C,
    int M, int N, int K, int act)
{
    __shared__ float As2[2][8][644];  // 32 chunks x (16 dup + 4 pad)
    __shared__ float Bs [2][8][164];  // 8 chunks x (16 + 4 pad)

    const int tid = threadIdx.x;
    const int tx  = tid & 7;           // n group: 16 n each
    const int ty  = tid >> 3;          // m group: 8 m each (0..31)
    const int m0  = blockIdx.y * 256;
    const int j0  = blockIdx.x * 128;

    // A loader (v5 style): row m0+tid, 8 k values (2x float4)
    const int aSoff = (tid >> 3) * 20 + (tid & 7) * 2;   // dup-pair float offset
    // B loader: row j0+(tid>>1), 4 k values at (tid&1)*4 (float4)
    const int bLr = tid >> 1;           // 0..127
    const int bLc = (tid & 1) * 4;      // {0,4}
    const bool bok = (j0 + bLr) < N;
    const int bSoff = (bLr >> 4) * 20 + (bLr & 15);
    const int nblk = (K + 7) >> 3;

    u64 acc[8][8];
#pragma unroll
    for (int i = 0; i < 8; i++)
#pragma unroll
        for (int j = 0; j < 8; j++) acc[i][j] = 0ull;

    float4 ra0, ra1, rb;
    const float4 z4 = make_float4(0.f, 0.f, 0.f, 0.f);

    auto LD = [&](int blk) {
        const int kg = blk * 8;
        ra0 = (kg < K)     ? *reinterpret_cast<const float4*>(&A[(size_t)(m0 + tid) * K + kg]) : z4;
        ra1 = (kg + 4 < K) ? *reinterpret_cast<const float4*>(&A[(size_t)(m0 + tid) * K + kg + 4]) : z4;
        const int kgb = kg + bLc;
        rb = (kgb < K && bok) ? *reinterpret_cast<const float4*>(&B[(size_t)(j0 + bLr) * K + kgb]) : z4;
    };
    auto ST = [&](int buf) {
        *reinterpret_cast<u64*>(&As2[buf][0][aSoff]) = dup2(ra0.x);
        *reinterpret_cast<u64*>(&As2[buf][1][aSoff]) = dup2(ra0.y);
        *reinterpret_cast<u64*>(&As2[buf][2][aSoff]) = dup2(ra0.z);
        *reinterpret_cast<u64*>(&As2[buf][3][aSoff]) = dup2(ra0.w);
        *reinterpret_cast<u64*>(&As2[buf][4][aSoff]) = dup2(ra1.x);
        *reinterpret_cast<u64*>(&As2[buf][5][aSoff]) = dup2(ra1.y);
        *reinterpret_cast<u64*>(&As2[buf][6][aSoff]) = dup2(ra1.z);
        *reinterpret_cast<u64*>(&As2[buf][7][aSoff]) = dup2(ra1.w);
        Bs[buf][bLc + 0][bSoff] = rb.x;
        Bs[buf][bLc + 1][bSoff] = rb.y;
        Bs[buf][bLc + 2][bSoff] = rb.z;
        Bs[buf][bLc + 3][bSoff] = rb.w;
    };

    LD(0); ST(0); __syncthreads();

    for (int blk = 0; blk < nblk; blk++) {
        const int buf = blk & 1;
        if (blk + 1 < nblk) LD(blk + 1);
#pragma unroll
        for (int k = 0; k < 8; k++) {
            const ulonglong2 ad01 = *reinterpret_cast<const ulonglong2*>(&As2[buf][k][ty * 20]);
            const ulonglong2 ad23 = *reinterpret_cast<const ulonglong2*>(&As2[buf][k][ty * 20 + 4]);
            const ulonglong2 ad45 = *reinterpret_cast<const ulonglong2*>(&As2[buf][k][ty * 20 + 8]);
            const ulonglong2 ad67 = *reinterpret_cast<const ulonglong2*>(&As2[buf][k][ty * 20 + 12]);
            const u64 ad[8] = {ad01.x, ad01.y, ad23.x, ad23.y,
                               ad45.x, ad45.y, ad67.x, ad67.y};
            const ulonglong2 b01 = *reinterpret_cast<const ulonglong2*>(&Bs[buf][k][tx * 20]);
            const ulonglong2 b23 = *reinterpret_cast<const ulonglong2*>(&Bs[buf][k][tx * 20 + 4]);
            const ulonglong2 b45 = *reinterpret_cast<const ulonglong2*>(&Bs[buf][k][tx * 20 + 8]);
            const ulonglong2 b67 = *reinterpret_cast<const ulonglong2*>(&Bs[buf][k][tx * 20 + 12]);
            const u64 b[8] = {b01.x, b01.y, b23.x, b23.y,
                              b45.x, b45.y, b67.x, b67.y};
#pragma unroll
            for (int mi = 0; mi < 8; mi++)
#pragma unroll
                for (int nj = 0; nj < 8; nj++) ffma2(acc[mi][nj], ad[mi], b[nj]);
        }
        if (blk + 1 < nblk) ST(buf ^ 1);
        __syncthreads();
    }

#pragma unroll
    for (int mi = 0; mi < 8; mi++) {
        const int m = m0 + ty * 8 + mi;
#pragma unroll
        for (int nj = 0; nj < 8; nj++) {
            const int n = j0 + tx * 16 + 2 * nj;
            if (n < N) {
                const float2 f = unpack2(acc[mi][nj]);
                float v0 = __fadd_rn(f.x, bias[n]);
                if (act) v0 = xla_logistic(v0);
                C[(size_t)m * N + n] = v0;
                if (n + 1 < N) {
                    float v1 = __fadd_rn(f.y, bias[n + 1]);
                    if (act) v1 = xla_logistic(v1);
                    C[(size_t)m * N + n + 1] = v1;
                }
            }
        }
    }
}

// ---------------------------------------------------------------------------
// Strict small GEMM (for K1): tile 64m x 64n x 8k, 256 threads, 4m x 4n/thread.
// ---------------------------------------------------------------------------
__global__ void __launch_bounds__(256) gemm_strict_small(
    const float* __restrict__ A, const float* __restrict__ B,
    const float* __restrict__ bias, float* __restrict__ C,
    int M, int N, int K, int act)
{
    __shared__ float As2[2][8][132];
    __shared__ float Bs [2][8][68];

    const int tid = threadIdx.x;
    const int tx  = tid & 15;
    const int ty  = tid >> 4;
    const int m0  = blockIdx.y * 64;
    const int j0  = blockIdx.x * 64;

    const int lr = tid >> 2;
    const int lc = (tid & 3) * 2;
    const bool bok = (j0 + lr) < N;
    const int nblk = (K + 7) >> 3;

    u64 acc[4][2];
#pragma unroll
    for (int i = 0; i < 4; i++) { acc[i][0] = 0ull; acc[i][1] = 0ull; }

    float2 ra, rb;

    auto LD = [&](int blk) {
        const int kg = blk * 8 + lc;
        const bool kok = kg < K;
        ra = kok ? *reinterpret_cast<const float2*>(&A[(size_t)(m0 + lr) * K + kg])
                 : make_float2(0.f, 0.f);
        rb = (kok && bok) ? *reinterpret_cast<const float2*>(&B[(size_t)(j0 + lr) * K + kg])
                          : make_float2(0.f, 0.f);
    };
    auto ST = [&](int buf) {
        *reinterpret_cast<u64*>(&As2[buf][lc + 0][2 * lr]) = dup2(ra.x);
        *reinterpret_cast<u64*>(&As2[buf][lc + 1][2 * lr]) = dup2(ra.y);
        Bs[buf][lc + 0][lr] = rb.x;
        Bs[buf][lc + 1][lr] = rb.y;
    };

    LD(0); ST(0); __syncthreads();

    for (int blk = 0; blk < nblk; blk++) {
        const int buf = blk & 1;
        if (blk + 1 < nblk) LD(blk + 1);
#pragma unroll
        for (int k = 0; k < 8; k++) {
            const ulonglong2 ad01 = *reinterpret_cast<const ulonglong2*>(&As2[buf][k][ty * 8]);
            const ulonglong2 ad23 = *reinterpret_cast<const ulonglong2*>(&As2[buf][k][ty * 8 + 4]);
            const u64 ad[4] = {ad01.x, ad01.y, ad23.x, ad23.y};
            const ulonglong2 bv = *reinterpret_cast<const ulonglong2*>(&Bs[buf][k][tx * 4]);
            const u64 b[2] = {bv.x, bv.y};
#pragma unroll
            for (int mi = 0; mi < 4; mi++) {
                ffma2(acc[mi][0], ad[mi], b[0]);
                ffma2(acc[mi][1], ad[mi], b[1]);
            }
        }
        if (blk + 1 < nblk) ST(buf ^ 1);
        __syncthreads();
    }

#pragma unroll
    for (int mi = 0; mi < 4; mi++) {
        const int m = m0 + ty * 4 + mi;
#pragma unroll
        for (int nj = 0; nj < 2; nj++) {
            const int n = j0 + tx * 4 + 2 * nj;
            if (n < N) {
                const float2 f = unpack2(acc[mi][nj]);
                float v0 = __fadd_rn(f.x, bias[n]);
                if (act) v0 = xla_logistic(v0);
                C[(size_t)m * N + n] = v0;
                if (n + 1 < N) {
                    float v1 = __fadd_rn(f.y, bias[n + 1]);
                    if (act) v1 = xla_logistic(v1);
                    C[(size_t)m * N + n + 1] = v1;
                }
            }
        }
    }
}

// ---- dummy: keeps K3 at the ncu-captured launch slot ------------------------
__global__ void k_dummy() {}

// ---- K2: cur2(t) for all t (IIR, no spike feedback; strict rounding) -------
__global__ void k2_cur2(const float* __restrict__ a1, const float* __restrict__ a2)
{
    const int idx = blockIdx.x * blockDim.x + threadIdx.x;
    if (idx >= NB * NH) return;
    const int j = idx % NH;
    const float c1 = a1[j], c2 = a2[j];
    const float va = __fmul_rn(V0F, d_ann[idx]);
    float p1 = 0.f, p2 = 0.f;
    for (int t = 0; t < TT; t++) {
        const float s = __fadd_rn(__fadd_rn(__fmul_rn(c1, p1), __fmul_rn(c2, p2)), va);
        d_cur[(size_t)t * NB * NH + idx] = s;
        p2 = p1; p1 = s;
    }
}

// ---- K45: fused layer-2 LIF + layer-3 IIR (strict; MLP-4 prefetch) ----------
__global__ void k45_lif2_cur3(const float* __restrict__ a1, const float* __restrict__ a2)
{
    const int idx = blockIdx.x * blockDim.x + threadIdx.x;
    if (idx >= NB * NH) return;
    const int j = idx % NH;
    const float c1 = a1[j], c2 = a2[j];
    float v = 0.f, ns = 1.f, p1 = 0.f, p2 = 0.f;
    for (int t0 = 0; t0 < TT; t0 += 4) {
        float w[4];
#pragma unroll
        for (int u = 0; u < 4; u++)
            w[u] = d_w2[(size_t)(t0 + u) * NB * NH + idx];
#pragma unroll
        for (int u = 0; u < 4; u++) {
            v = __fadd_rn(__fmul_rn(__fmul_rn(SIGF, v), ns), w[u]);
            const bool s = (__fadd_rn(v, -1.0f) > 0.f);
            ns = s ? 0.f : 1.f;
            const float inp = s ? V0F : 0.f;
            const float c = __fadd_rn(__fadd_rn(__fmul_rn(c1, p1), __fmul_rn(c2, p2)), inp);
            d_cur[(size_t)(t0 + u) * NB * NH + idx] = c;
            p2 = p1; p1 = c;
        }
    }
}

// ---- K6: w3 = cur3 @ W3^T + b3  (strict k-chain; float4 LDS) ----------------
__global__ void __launch_bounds__(640) k6_gemm3(const float* __restrict__ W3,
                                                const float* __restrict__ b3)
{
    __shared__ float W3s[NO * NH];   // 20 KB
    __shared__ float Cs[64][68];     // padded for float4 alignment
    const int tid = threadIdx.x;
    const int r0 = blockIdx.x * 64;
    for (int i = tid; i < NO * NH; i += 640) W3s[i] = W3[i];
    const int rr = tid / 10, o = tid - rr * 10;
    float acc = 0.f;
    for (int k0 = 0; k0 < NH; k0 += 64) {
        __syncthreads();
        for (int i = tid; i < 64 * 64; i += 640) {
            const int r = i >> 6, kq = i & 63, kg = k0 + kq;
            Cs[r][kq] = (kg < NH) ? d_cur[(size_t)(r0 + r) * NH + kg] : 0.f;
        }
        __syncthreads();
        const int kl = (NH - k0 < 64) ? (NH - k0) : 64;   // 64 or 52 (mult of 4)
        for (int k = 0; k < kl; k += 4) {
            const float4 c = *reinterpret_cast<const float4*>(&Cs[rr][k]);
            const float4 w = *reinterpret_cast<const float4*>(&W3s[o * NH + k0 + k]);
            acc = fmaf(c.x, w.x, acc);
            acc = fmaf(c.y, w.y, acc);
            acc = fmaf(c.z, w.z, acc);
            acc = fmaf(c.w, w.w, acc);
        }
    }
    d_w3[(size_t)(r0 + rr) * NO + o] = __fadd_rn(acc, b3[o]);
}

// ---- K7: layer-3 LIF scan -> output [B,10,T] --------------------------------
__global__ void k7_lif3(float* __restrict__ out)
{
    const int idx = blockIdx.x * blockDim.x + threadIdx.x;
    if (idx >= NB * NO) return;
    const int b = idx / NO, o = idx - b * NO;
    float v = 0.f, ns = 1.f;
    for (int t0 = 0; t0 < TT; t0 += 4) {
        float w[4];
#pragma unroll
        for (int u = 0; u < 4; u++)
            w[u] = d_w3[((size_t)(t0 + u) * NB + b) * NO + o];
#pragma unroll
        for (int u = 0; u < 4; u++) {
            v = __fadd_rn(__fmul_rn(__fmul_rn(SIGF, v), ns), w[u]);
            const bool s = (__fadd_rn(v, -1.0f) > 0.f);
            ns = s ? 0.f : 1.f;
            out[((size_t)b * NO + o) * TT + t0 + u] = s ? 1.f : 0.f;
        }
    }
}

// ---------------------------------------------------------------------------
extern "C" void kernel_launch(void* const* d_in, const int* in_sizes, int n_in,
                              void* d_out, int out_size)
{
    const float* inputs = (const float*)d_in[0];
    const float* W1     = (const float*)d_in[1];
    const float* b1     = (const float*)d_in[2];
    const float* a1_2   = (const float*)d_in[3];
    const float* a2_2   = (const float*)d_in[4];
    const float* W2     = (const float*)d_in[5];
    const float* b2     = (const float*)d_in[6];
    const float* a1_3   = (const float*)d_in[7];
    const float* a2_3   = (const float*)d_in[8];
    const float* W3     = (const float*)d_in[9];
    const float* b3     = (const float*)d_in[10];

    float* ann; cudaGetSymbolAddress((void**)&ann, d_ann);
    float* cur; cudaGetSymbolAddress((void**)&cur, d_cur);
    float* w2;  cudaGetSymbolAddress((void**)&w2,  d_w2);

    const int NRR = TT * NB;   // 51200

    // K1: ann = logistic(inputs @ W1^T + b1)     (M=256, K=784) — 32 CTAs
    gemm_strict_small<<<dim3(8, NB / 64), 256>>>(inputs, W1, b1, ann, NB, NH, NI, 1);
    // K2: cur2 for all t
    k2_cur2<<<(NB * NH + 255) / 256, 256>>>(a1_2, a2_2);
    // dummy (keeps K3 at the ncu-captured launch slot)
    k_dummy<<<1, 1>>>();
    // K3: w2 = cur2_all @ W2^T + b2              (M=51200, K=500)
    gemm_strict_v7<<<dim3(4, NRR / 256), 256>>>(cur, W2, b2, w2, NRR, NH, NH, 0);
    // K45: layer-2 LIF + layer-3 synapse IIR (fused)
    k45_lif2_cur3<<<(NB * NH + 255) / 256, 256>>>(a1_3, a2_3);
    // K6: w3 = cur3_all @ W3^T + b3
    k6_gemm3<<<NRR / 64, 640>>>(W3, b3);
    // K7: layer-3 LIF -> output
    k7_lif3<<<(NB * NO + 255) / 256, 256>>>((float*)d_out);
}

// round 12
// speedup vs baseline: 1.1480x; 1.1480x over previous
#include <cuda_runtime.h>

#define NB 256
#define NH 500
#define NI 784
#define NO 10
#define TT 200
#define NRR (TT*NB)          // 51200 rows
#define NP 63                // ceil(NH/8) k-panels

#define V0F  2.1165347359575993f   // f32(eta^(eta/(eta-1))/(eta-1)), eta=4
#define SIGF 0.7788007830714049f   // f32(exp(-1/4))

typedef unsigned long long u64;

// static device scratch (allowed per harness rules)
__device__ float d_ann[NB*NH];
__device__ float d_curp[(size_t)NP*NRR*8];  // 103.2 MB, 8-k panel layout
__device__ float d_w2[(size_t)TT*NB*NH];    // 102.4 MB
__device__ float d_w3[TT*NB*NO];            // 2 MB

__device__ __forceinline__ void ffma2(u64 &acc, u64 a, u64 b) {
    asm("fma.rn.f32x2 %0, %1, %2, %0;" : "+l"(acc) : "l"(a), "l"(b));
}
__device__ __forceinline__ float2 unpack2(u64 v) {
    float2 f; asm("mov.b64 {%0,%1}, %2;" : "=f"(f.x), "=f"(f.y) : "l"(v));
    return f;
}
__device__ __forceinline__ u64 dup2(float v) {
    u64 d; asm("mov.b64 %0, {%1, %1};" : "=l"(d) : "f"(v)); return d;
}

// XLA f32 tanh (rational approx, strict unfused) + logistic expansion
__device__ __forceinline__ float xla_tanh(float x) {
    const float xc = fminf(fmaxf(x, -7.90531110763549805f), 7.90531110763549805f);
    const float x2 = __fmul_rn(xc, xc);
    float p = -2.76076847742355e-16f;
    p = __fadd_rn(__fmul_rn(p, x2),  2.00018790482477e-13f);
    p = __fadd_rn(__fmul_rn(p, x2), -8.60467152213735e-11f);
    p = __fadd_rn(__fmul_rn(p, x2),  5.12229709037114e-08f);
    p = __fadd_rn(__fmul_rn(p, x2),  1.48572235717979e-05f);
    p = __fadd_rn(__fmul_rn(p, x2),  6.37261928875436e-04f);
    p = __fadd_rn(__fmul_rn(p, x2),  4.89352455891786e-03f);
    const float num = __fmul_rn(xc, p);
    float q = 1.19825839466702e-06f;
    q = __fadd_rn(__fmul_rn(q, x2), 1.18534705686654e-04f);
    q = __fadd_rn(__fmul_rn(q, x2), 2.26843463243900e-03f);
    q = __fadd_rn(__fmul_rn(q, x2), 4.89352518554385e-03f);
    const float t = __fdiv_rn(num, q);
    return (fabsf(x) < 0.0004f) ? x : t;
}
__device__ __forceinline__ float xla_logistic(float z) {
    return __fadd_rn(0.5f, __fmul_rn(0.5f, xla_tanh(__fmul_rn(0.5f, z))));
}

// ---------------------------------------------------------------------------
// Strict GEMM v8: w2[m,n] = chain_k fma(cur[m,k], W2[n,k]) + b2[n]
// = v5 compute core (tile 256m x 64n x 8k, 256 thr, 2 CTA/SM, padded dup-A
// smem, conflict-free LDS.128) with A read from the 8-k PANEL layout:
// each thread loads 8 consecutive floats (2 adjacent float4, coalesced),
// cutting A-LDG from 32 to ~4 wavefronts per instruction.
// Per output: single accumulator, strictly k-ascending fma.rn chain.
// ---------------------------------------------------------------------------
__global__ void __launch_bounds__(256, 2) gemm_strict_v8(
    const float* __restrict__ Ap,   // panels [NP][M][8]
    const float* __restrict__ B,    // [N][K] row-major
    const float* __restrict__ bias, float* __restrict__ C,
    int M, int N, int K)
{
    __shared__ float As2[2][8][644];  // 32 chunks x (16 dup + 4 pad)
    __shared__ float Bs [2][8][100];  // 8 chunks x (8 + 4 pad)

    const int tid = threadIdx.x;
    const int tx  = tid & 7;           // n group: 8 n each
    const int ty  = tid >> 3;          // m group: 8 m each (0..31)
    const int m0  = blockIdx.y * 256;
    const int j0  = blockIdx.x * 64;

    const int bLr = tid >> 2;          // 0..63
    const int bLc = (tid & 3) * 2;     // {0,2,4,6}
    const bool bok = (j0 + bLr) < N;
    const int aSoff = (tid >> 3) * 20 + (tid & 7) * 2;   // dup-pair offset
    const int bSoff = (bLr >> 3) * 12 + (bLr & 7);
    const int nblk = (K + 7) >> 3;     // 63

    u64 acc[8][4];
#pragma unroll
    for (int i = 0; i < 8; i++)
#pragma unroll
        for (int j = 0; j < 4; j++) acc[i][j] = 0ull;

    float4 ra0, ra1; float2 rb;

    auto LD = [&](int blk) {
        // panel blk, row m0+tid: 8 consecutive floats (fully coalesced)
        const float4* src = reinterpret_cast<const float4*>(
            Ap + ((size_t)blk * M + m0 + tid) * 8);
        ra0 = src[0];
        ra1 = src[1];
        const int kgb = blk * 8 + bLc;
        rb = (kgb < K && bok) ? *reinterpret_cast<const float2*>(&B[(size_t)(j0 + bLr) * K + kgb])
                              : make_float2(0.f, 0.f);
    };
    auto ST = [&](int buf) {
        *reinterpret_cast<u64*>(&As2[buf][0][aSoff]) = dup2(ra0.x);
        *reinterpret_cast<u64*>(&As2[buf][1][aSoff]) = dup2(ra0.y);
        *reinterpret_cast<u64*>(&As2[buf][2][aSoff]) = dup2(ra0.z);
        *reinterpret_cast<u64*>(&As2[buf][3][aSoff]) = dup2(ra0.w);
        *reinterpret_cast<u64*>(&As2[buf][4][aSoff]) = dup2(ra1.x);
        *reinterpret_cast<u64*>(&As2[buf][5][aSoff]) = dup2(ra1.y);
        *reinterpret_cast<u64*>(&As2[buf][6][aSoff]) = dup2(ra1.z);
        *reinterpret_cast<u64*>(&As2[buf][7][aSoff]) = dup2(ra1.w);
        Bs[buf][bLc + 0][bSoff] = rb.x;
        Bs[buf][bLc + 1][bSoff] = rb.y;
    };

    LD(0); ST(0); __syncthreads();

    for (int blk = 0; blk < nblk; blk++) {
        const int buf = blk & 1;
        if (blk + 1 < nblk) LD(blk + 1);
#pragma unroll
        for (int k = 0; k < 8; k++) {
            const ulonglong2 ad01 = *reinterpret_cast<const ulonglong2*>(&As2[buf][k][ty * 20]);
            const ulonglong2 ad23 = *reinterpret_cast<const ulonglong2*>(&As2[buf][k][ty * 20 + 4]);
            const ulonglong2 ad45 = *reinterpret_cast<const ulonglong2*>(&As2[buf][k][ty * 20 + 8]);
            const ulonglong2 ad67 = *reinterpret_cast<const ulonglong2*>(&As2[buf][k][ty * 20 + 12]);
            const u64 ad[8] = {ad01.x, ad01.y, ad23.x, ad23.y,
                               ad45.x, ad45.y, ad67.x, ad67.y};
            const ulonglong2 b01 = *reinterpret_cast<const ulonglong2*>(&Bs[buf][k][tx * 12]);
            const ulonglong2 b23 = *reinterpret_cast<const ulonglong2*>(&Bs[buf][k][tx * 12 + 4]);
            const u64 b[4] = {b01.x, b01.y, b23.x, b23.y};
#pragma unroll
            for (int mi = 0; mi < 8; mi++)
#pragma unroll
                for (int nj = 0; nj < 4; nj++) ffma2(acc[mi][nj], ad[mi], b[nj]);
        }
        if (blk + 1 < nblk) ST(buf ^ 1);
        __syncthreads();
    }

#pragma unroll
    for (int mi = 0; mi < 8; mi++) {
        const int m = m0 + ty * 8 + mi;
#pragma unroll
        for (int nj = 0; nj < 4; nj++) {
            const int n = j0 + tx * 8 + 2 * nj;
            if (n < N) {
                const float2 f = unpack2(acc[mi][nj]);
                C[(size_t)m * N + n] = __fadd_rn(f.x, bias[n]);
                if (n + 1 < N)
                    C[(size_t)m * N + n + 1] = __fadd_rn(f.y, bias[n + 1]);
            }
        }
    }
}

// ---------------------------------------------------------------------------
// Strict small GEMM (for K1): tile 64m x 64n x 8k, 256 threads, 4m x 4n/thread.
// ---------------------------------------------------------------------------
__global__ void __launch_bounds__(256) gemm_strict_small(
    const float* __restrict__ A, const float* __restrict__ B,
    const float* __restrict__ bias, float* __restrict__ C,
    int M, int N, int K, int act)
{
    __shared__ float As2[2][8][132];
    __shared__ float Bs [2][8][68];

    const int tid = threadIdx.x;
    const int tx  = tid & 15;
    const int ty  = tid >> 4;
    const int m0  = blockIdx.y * 64;
    const int j0  = blockIdx.x * 64;

    const int lr = tid >> 2;
    const int lc = (tid & 3) * 2;
    const bool bok = (j0 + lr) < N;
    const int nblk = (K + 7) >> 3;

    u64 acc[4][2];
#pragma unroll
    for (int i = 0; i < 4; i++) { acc[i][0] = 0ull; acc[i][1] = 0ull; }

    float2 ra, rb;

    auto LD = [&](int blk) {
        const int kg = blk * 8 + lc;
        const bool kok = kg < K;
        ra = kok ? *reinterpret_cast<const float2*>(&A[(size_t)(m0 + lr) * K + kg])
                 : make_float2(0.f, 0.f);
        rb = (kok && bok) ? *reinterpret_cast<const float2*>(&B[(size_t)(j0 + lr) * K + kg])
                          : make_float2(0.f, 0.f);
    };
    auto ST = [&](int buf) {
        *reinterpret_cast<u64*>(&As2[buf][lc + 0][2 * lr]) = dup2(ra.x);
        *reinterpret_cast<u64*>(&As2[buf][lc + 1][2 * lr]) = dup2(ra.y);
        Bs[buf][lc + 0][lr] = rb.x;
        Bs[buf][lc + 1][lr] = rb.y;
    };

    LD(0); ST(0); __syncthreads();

    for (int blk = 0; blk < nblk; blk++) {
        const int buf = blk & 1;
        if (blk + 1 < nblk) LD(blk + 1);
#pragma unroll
        for (int k = 0; k < 8; k++) {
            const ulonglong2 ad01 = *reinterpret_cast<const ulonglong2*>(&As2[buf][k][ty * 8]);
            const ulonglong2 ad23 = *reinterpret_cast<const ulonglong2*>(&As2[buf][k][ty * 8 + 4]);
            const u64 ad[4] = {ad01.x, ad01.y, ad23.x, ad23.y};
            const ulonglong2 bv = *reinterpret_cast<const ulonglong2*>(&Bs[buf][k][tx * 4]);
            const u64 b[2] = {bv.x, bv.y};
#pragma unroll
            for (int mi = 0; mi < 4; mi++) {
                ffma2(acc[mi][0], ad[mi], b[0]);
                ffma2(acc[mi][1], ad[mi], b[1]);
            }
        }
        if (blk + 1 < nblk) ST(buf ^ 1);
        __syncthreads();
    }

#pragma unroll
    for (int mi = 0; mi < 4; mi++) {
        const int m = m0 + ty * 4 + mi;
#pragma unroll
        for (int nj = 0; nj < 2; nj++) {
            const int n = j0 + tx * 4 + 2 * nj;
            if (n < N) {
                const float2 f = unpack2(acc[mi][nj]);
                float v0 = __fadd_rn(f.x, bias[n]);
                if (act) v0 = xla_logistic(v0);
                C[(size_t)m * N + n] = v0;
                if (n + 1 < N) {
                    float v1 = __fadd_rn(f.y, bias[n + 1]);
                    if (act) v1 = xla_logistic(v1);
                    C[(size_t)m * N + n + 1] = v1;
                }
            }
        }
    }
}

// ---- dummy: keeps K3 at the ncu-captured launch slot ------------------------
__global__ void k_dummy() {}

// ---- K2: cur2(t) for all t -> panel layout (strict rounding) ----------------
__global__ void k2_cur2(const float* __restrict__ a1, const float* __restrict__ a2)
{
    const int idx = blockIdx.x * blockDim.x + threadIdx.x;
    if (idx >= NB * NH) return;
    const int b = idx / NH, j = idx - (idx / NH) * NH;
    const float c1 = a1[j], c2 = a2[j];
    const float va = __fmul_rn(V0F, d_ann[idx]);
    float* dst = d_curp + ((size_t)(j >> 3) * NRR + b) * 8 + (j & 7);
    float p1 = 0.f, p2 = 0.f;
    for (int t = 0; t < TT; t++) {
        const float s = __fadd_rn(__fadd_rn(__fmul_rn(c1, p1), __fmul_rn(c2, p2)), va);
        dst[(size_t)t * NB * 8] = s;
        p2 = p1; p1 = s;
    }
}

// ---- K45: fused layer-2 LIF + layer-3 IIR -> panel layout -------------------
__global__ void k45_lif2_cur3(const float* __restrict__ a1, const float* __restrict__ a2)
{
    const int idx = blockIdx.x * blockDim.x + threadIdx.x;
    if (idx >= NB * NH) return;
    const int b = idx / NH, j = idx - (idx / NH) * NH;
    const float c1 = a1[j], c2 = a2[j];
    float* dst = d_curp + ((size_t)(j >> 3) * NRR + b) * 8 + (j & 7);
    float v = 0.f, ns = 1.f, p1 = 0.f, p2 = 0.f;
    for (int t0 = 0; t0 < TT; t0 += 4) {
        float w[4];
#pragma unroll
        for (int u = 0; u < 4; u++)
            w[u] = d_w2[(size_t)(t0 + u) * NB * NH + idx];
#pragma unroll
        for (int u = 0; u < 4; u++) {
            v = __fadd_rn(__fmul_rn(__fmul_rn(SIGF, v), ns), w[u]);
            const bool s = (__fadd_rn(v, -1.0f) > 0.f);
            ns = s ? 0.f : 1.f;
            const float inp = s ? V0F : 0.f;
            const float c = __fadd_rn(__fadd_rn(__fmul_rn(c1, p1), __fmul_rn(c2, p2)), inp);
            dst[(size_t)(t0 + u) * NB * 8] = c;
            p2 = p1; p1 = c;
        }
    }
}

// ---- K6: w3 = cur3 @ W3^T + b3  (strict k-chain; panel A reads) -------------
__global__ void __launch_bounds__(640) k6_gemm3(const float* __restrict__ W3,
                                                const float* __restrict__ b3)
{
    __shared__ float W3s[NO * NH];   // 20 KB
    __shared__ float Cs[64][68];     // padded for float4 alignment
    const int tid = threadIdx.x;
    const int r0 = blockIdx.x * 64;
    for (int i = tid; i < NO * NH; i += 640) W3s[i] = W3[i];
    const int rr = tid / 10, o = tid - rr * 10;
    float acc = 0.f;
    for (int k0 = 0; k0 < NH; k0 += 64) {
        __syncthreads();
        for (int i = tid; i < 64 * 64; i += 640) {
            const int r = i >> 6, kq = i & 63, kg = k0 + kq;
            Cs[r][kq] = (kg < NH)
                ? d_curp[((size_t)(kg >> 3) * NRR + r0 + r) * 8 + (kg & 7)] : 0.f;
        }
        __syncthreads();
        const int kl = (NH - k0 < 64) ? (NH - k0) : 64;   // 64 or 52 (mult of 4)
        for (int k = 0; k < kl; k += 4) {
            const float4 c = *reinterpret_cast<const float4*>(&Cs[rr][k]);
            const float4 w = *reinterpret_cast<const float4*>(&W3s[o * NH + k0 + k]);
            acc = fmaf(c.x, w.x, acc);
            acc = fmaf(c.y, w.y, acc);
            acc = fmaf(c.z, w.z, acc);
            acc = fmaf(c.w, w.w, acc);
        }
    }
    d_w3[(size_t)(r0 + rr) * NO + o] = __fadd_rn(acc, b3[o]);
}

// ---- K7: layer-3 LIF scan -> output [B,10,T] --------------------------------
__global__ void k7_lif3(float* __restrict__ out)
{
    const int idx = blockIdx.x * blockDim.x + threadIdx.x;
    if (idx >= NB * NO) return;
    const int b = idx / NO, o = idx - b * NO;
    float v = 0.f, ns = 1.f;
    for (int t0 = 0; t0 < TT; t0 += 4) {
        float w[4];
#pragma unroll
        for (int u = 0; u < 4; u++)
            w[u] = d_w3[((size_t)(t0 + u) * NB + b) * NO + o];
#pragma unroll
        for (int u = 0; u < 4; u++) {
            v = __fadd_rn(__fmul_rn(__fmul_rn(SIGF, v), ns), w[u]);
            const bool s = (__fadd_rn(v, -1.0f) > 0.f);
            ns = s ? 0.f : 1.f;
            out[((size_t)b * NO + o) * TT + t0 + u] = s ? 1.f : 0.f;
        }
    }
}

// ---------------------------------------------------------------------------
extern "C" void kernel_launch(void* const* d_in, const int* in_sizes, int n_in,
                              void* d_out, int out_size)
{
    const float* inputs = (const float*)d_in[0];
    const float* W1     = (const float*)d_in[1];
    const float* b1     = (const float*)d_in[2];
    const float* a1_2   = (const float*)d_in[3];
    const float* a2_2   = (const float*)d_in[4];
    const float* W2     = (const float*)d_in[5];
    const float* b2     = (const float*)d_in[6];
    const float* a1_3   = (const float*)d_in[7];
    const float* a2_3   = (const float*)d_in[8];
    const float* W3     = (const float*)d_in[9];
    const float* b3     = (const float*)d_in[10];

    float* ann;  cudaGetSymbolAddress((void**)&ann,  d_ann);
    float* curp; cudaGetSymbolAddress((void**)&curp, d_curp);
    float* w2;   cudaGetSymbolAddress((void**)&w2,   d_w2);

    // K1: ann = logistic(inputs @ W1^T + b1)     (M=256, K=784) — 32 CTAs
    gemm_strict_small<<<dim3(8, NB / 64), 256>>>(inputs, W1, b1, ann, NB, NH, NI, 1);
    // K2: cur2 for all t (panel layout)
    k2_cur2<<<(NB * NH + 255) / 256, 256>>>(a1_2, a2_2);
    // dummy (keeps K3 at the ncu-captured launch slot)
    k_dummy<<<1, 1>>>();
    // K3: w2 = cur2_all @ W2^T + b2              (M=51200, K=500)
    gemm_strict_v8<<<dim3(8, NRR / 256), 256>>>(curp, W2, b2, w2, NRR, NH, NH);
    // K45: layer-2 LIF + layer-3 synapse IIR (fused, panel writes)
    k45_lif2_cur3<<<(NB * NH + 255) / 256, 256>>>(a1_3, a2_3);
    // K6: w3 = cur3_all @ W3^T + b3
    k6_gemm3<<<NRR / 64, 640>>>(W3, b3);
    // K7: layer-3 LIF -> output
    k7_lif3<<<(NB * NO + 255) / 256, 256>>>((float*)d_out);
}

// round 13
// speedup vs baseline: 1.2936x; 1.1268x over previous
#include <cuda_runtime.h>

#define NB 256
#define NH 500
#define NI 784
#define NO 10
#define TT 200
#define NRR (TT*NB)          // 51200 rows
#define NP 63                // ceil(NH/8) k-panels

#define V0F  2.1165347359575993f   // f32(eta^(eta/(eta-1))/(eta-1)), eta=4
#define SIGF 0.7788007830714049f   // f32(exp(-1/4))

typedef unsigned long long u64;

// static device scratch (allowed per harness rules)
__device__ float d_ann[NB*NH];
__device__ float d_curp[(size_t)NP*NRR*8];  // 103.2 MB, 8-k panel layout
__device__ float d_w2[(size_t)TT*NB*NH];    // 102.4 MB
__device__ float d_w3[TT*NB*NO];            // 2 MB

__device__ __forceinline__ void ffma2(u64 &acc, u64 a, u64 b) {
    asm("fma.rn.f32x2 %0, %1, %2, %0;" : "+l"(acc) : "l"(a), "l"(b));
}
__device__ __forceinline__ float2 unpack2(u64 v) {
    float2 f; asm("mov.b64 {%0,%1}, %2;" : "=f"(f.x), "=f"(f.y) : "l"(v));
    return f;
}
__device__ __forceinline__ u64 swap2(u64 v) {
    float2 f = unpack2(v);
    u64 s; asm("mov.b64 %0, {%1, %2};" : "=l"(s) : "f"(f.y), "f"(f.x));
    return s;
}

// XLA f32 tanh (rational approx, strict unfused) + logistic expansion
__device__ __forceinline__ float xla_tanh(float x) {
    const float xc = fminf(fmaxf(x, -7.90531110763549805f), 7.90531110763549805f);
    const float x2 = __fmul_rn(xc, xc);
    float p = -2.76076847742355e-16f;
    p = __fadd_rn(__fmul_rn(p, x2),  2.00018790482477e-13f);
    p = __fadd_rn(__fmul_rn(p, x2), -8.60467152213735e-11f);
    p = __fadd_rn(__fmul_rn(p, x2),  5.12229709037114e-08f);
    p = __fadd_rn(__fmul_rn(p, x2),  1.48572235717979e-05f);
    p = __fadd_rn(__fmul_rn(p, x2),  6.37261928875436e-04f);
    p = __fadd_rn(__fmul_rn(p, x2),  4.89352455891786e-03f);
    const float num = __fmul_rn(xc, p);
    float q = 1.19825839466702e-06f;
    q = __fadd_rn(__fmul_rn(q, x2), 1.18534705686654e-04f);
    q = __fadd_rn(__fmul_rn(q, x2), 2.26843463243900e-03f);
    q = __fadd_rn(__fmul_rn(q, x2), 4.89352518554385e-03f);
    const float t = __fdiv_rn(num, q);
    return (fabsf(x) < 0.0004f) ? x : t;
}
__device__ __forceinline__ float xla_logistic(float z) {
    return __fadd_rn(0.5f, __fmul_rn(0.5f, xla_tanh(__fmul_rn(0.5f, z))));
}

// ---------------------------------------------------------------------------
// Strict GEMM v9: w2[m,n] = chain_k fma(cur[m,k], W2[n,k]) + b2[n]
// Tile 256m x 64n x 8k, 256 threads, 2 CTA/SM, double-buffered.
// NO operand duplication: A and B both stored as natural pairs in
// 12-float-strided chunks (bank-conflict-free). Each 2x2 output block uses
// two diagonal accumulators:
//   accD = (C[m][n],   C[m+1][n+1])  <- a_pair * b_pair
//   accX = (C[m][n+1], C[m+1][n])    <- a_pair * swap(b_pair)
// Compute LDS = 4 x LDS.128 / thread / k (1.0 B/FMA). Swapped b built with
// 2 MOVs/pair on the idle alu pipe. Per output element: single accumulator,
// strictly k-ascending fma.rn chain (bit-exact vs reference).
// ---------------------------------------------------------------------------
__global__ void __launch_bounds__(256, 2) gemm_strict_v9(
    const float* __restrict__ Ap,   // panels [NP][M][8]
    const float* __restrict__ B,    // [N][K] row-major
    const float* __restrict__ bias, float* __restrict__ C,
    int M, int N, int K)
{
    __shared__ float As[2][8][388];  // 32 chunks x (8 + 4 pad)
    __shared__ float Bs[2][8][100];  // 8 chunks x (8 + 4 pad)

    const int tid = threadIdx.x;
    const int tx  = tid & 7;           // n group: 8 n each
    const int ty  = tid >> 3;          // m chunk: 8 m each (0..31)
    const int m0  = blockIdx.y * 256;
    const int j0  = blockIdx.x * 64;

    const int bLr = tid >> 2;          // 0..63
    const int bLc = (tid & 3) * 2;     // {0,2,4,6}
    const bool bok = (j0 + bLr) < N;
    const int aSoff = (tid >> 3) * 12 + (tid & 7);   // natural slot
    const int bSoff = (bLr >> 3) * 12 + (bLr & 7);
    const int nblk = (K + 7) >> 3;     // 63

    u64 accD[4][4], accX[4][4];
#pragma unroll
    for (int i = 0; i < 4; i++)
#pragma unroll
        for (int j = 0; j < 4; j++) { accD[i][j] = 0ull; accX[i][j] = 0ull; }

    float4 ra0, ra1; float2 rb;

    auto LD = [&](int blk) {
        const float4* src = reinterpret_cast<const float4*>(
            Ap + ((size_t)blk * M + m0 + tid) * 8);
        ra0 = src[0];
        ra1 = src[1];
        const int kgb = blk * 8 + bLc;
        rb = (kgb < K && bok) ? *reinterpret_cast<const float2*>(&B[(size_t)(j0 + bLr) * K + kgb])
                              : make_float2(0.f, 0.f);
    };
    auto ST = [&](int buf) {
        As[buf][0][aSoff] = ra0.x;  As[buf][1][aSoff] = ra0.y;
        As[buf][2][aSoff] = ra0.z;  As[buf][3][aSoff] = ra0.w;
        As[buf][4][aSoff] = ra1.x;  As[buf][5][aSoff] = ra1.y;
        As[buf][6][aSoff] = ra1.z;  As[buf][7][aSoff] = ra1.w;
        Bs[buf][bLc + 0][bSoff] = rb.x;
        Bs[buf][bLc + 1][bSoff] = rb.y;
    };

    LD(0); ST(0); __syncthreads();

    for (int blk = 0; blk < nblk; blk++) {
        const int buf = blk & 1;
        if (blk + 1 < nblk) LD(blk + 1);
#pragma unroll
        for (int k = 0; k < 8; k++) {
            const ulonglong2 a01 = *reinterpret_cast<const ulonglong2*>(&As[buf][k][ty * 12]);
            const ulonglong2 a23 = *reinterpret_cast<const ulonglong2*>(&As[buf][k][ty * 12 + 4]);
            const u64 a[4] = {a01.x, a01.y, a23.x, a23.y};
            const ulonglong2 b01 = *reinterpret_cast<const ulonglong2*>(&Bs[buf][k][tx * 12]);
            const ulonglong2 b23 = *reinterpret_cast<const ulonglong2*>(&Bs[buf][k][tx * 12 + 4]);
            const u64 b[4]  = {b01.x, b01.y, b23.x, b23.y};
            const u64 bs[4] = {swap2(b[0]), swap2(b[1]), swap2(b[2]), swap2(b[3])};
#pragma unroll
            for (int mi = 0; mi < 4; mi++)
#pragma unroll
                for (int nj = 0; nj < 4; nj++) {
                    ffma2(accD[mi][nj], a[mi], b[nj]);
                    ffma2(accX[mi][nj], a[mi], bs[nj]);
                }
        }
        if (blk + 1 < nblk) ST(buf ^ 1);
        __syncthreads();
    }

#pragma unroll
    for (int mi = 0; mi < 4; mi++) {
        const int m = m0 + ty * 8 + 2 * mi;
#pragma unroll
        for (int nj = 0; nj < 4; nj++) {
            const int n = j0 + tx * 8 + 2 * nj;
            const float2 D = unpack2(accD[mi][nj]);
            const float2 X = unpack2(accX[mi][nj]);
            if (n < N) {
                const float bn = bias[n];
                C[(size_t)m * N + n]       = __fadd_rn(D.x, bn);
                C[(size_t)(m + 1) * N + n] = __fadd_rn(X.y, bn);
            }
            if (n + 1 < N) {
                const float bn1 = bias[n + 1];
                C[(size_t)m * N + n + 1]       = __fadd_rn(X.x, bn1);
                C[(size_t)(m + 1) * N + n + 1] = __fadd_rn(D.y, bn1);
            }
        }
    }
}

// ---------------------------------------------------------------------------
// K1 GEMM: 32m x 32n x 16k tiles, 256 threads (16x16), 2m x 2n per thread.
// 128 CTAs (full chip). Strict k-ascending fmaf chain + XLA logistic.
// Requires: M % 32 == 0, K % 16 == 0.
// ---------------------------------------------------------------------------
__global__ void __launch_bounds__(256) gemm_k1(
    const float* __restrict__ A, const float* __restrict__ B,
    const float* __restrict__ bias, float* __restrict__ C,
    int M, int N, int K)
{
    __shared__ float As[2][16][36];
    __shared__ float Bs[2][16][36];

    const int tid = threadIdx.x;
    const int tx  = tid & 15;
    const int ty  = tid >> 4;
    const int m0  = blockIdx.y * 32;
    const int j0  = blockIdx.x * 32;

    const int lr = tid >> 3;          // 0..31
    const int lc = (tid & 7) * 2;     // 0..14
    const bool bok = (j0 + lr) < N;
    const int nblk = K / 16;

    float acc[2][2] = {{0.f, 0.f}, {0.f, 0.f}};
    float2 ra, rb;

    auto LD = [&](int blk) {
        const int kg = blk * 16 + lc;
        ra = *reinterpret_cast<const float2*>(&A[(size_t)(m0 + lr) * K + kg]);
        rb = bok ? *reinterpret_cast<const float2*>(&B[(size_t)(j0 + lr) * K + kg])
                 : make_float2(0.f, 0.f);
    };
    auto ST = [&](int buf) {
        As[buf][lc + 0][lr] = ra.x;  As[buf][lc + 1][lr] = ra.y;
        Bs[buf][lc + 0][lr] = rb.x;  Bs[buf][lc + 1][lr] = rb.y;
    };

    LD(0); ST(0); __syncthreads();

    for (int blk = 0; blk < nblk; blk++) {
        const int buf = blk & 1;
        if (blk + 1 < nblk) LD(blk + 1);
#pragma unroll
        for (int k = 0; k < 16; k++) {
            const float a0 = As[buf][k][ty * 2], a1 = As[buf][k][ty * 2 + 1];
            const float b0 = Bs[buf][k][tx * 2], b1 = Bs[buf][k][tx * 2 + 1];
            acc[0][0] = fmaf(a0, b0, acc[0][0]);
            acc[0][1] = fmaf(a0, b1, acc[0][1]);
            acc[1][0] = fmaf(a1, b0, acc[1][0]);
            acc[1][1] = fmaf(a1, b1, acc[1][1]);
        }
        if (blk + 1 < nblk) ST(buf ^ 1);
        __syncthreads();
    }

#pragma unroll
    for (int i = 0; i < 2; i++) {
        const int m = m0 + ty * 2 + i;
#pragma unroll
        for (int j = 0; j < 2; j++) {
            const int n = j0 + tx * 2 + j;
            if (n < N)
                C[(size_t)m * N + n] = xla_logistic(__fadd_rn(acc[i][j], bias[n]));
        }
    }
}

// ---- dummy: keeps K3 at the ncu-captured launch slot ------------------------
__global__ void k_dummy() {}

// ---- K2: cur2(t) for all t -> panel layout (strict rounding) ----------------
__global__ void k2_cur2(const float* __restrict__ a1, const float* __restrict__ a2)
{
    const int idx = blockIdx.x * blockDim.x + threadIdx.x;
    if (idx >= NB * NH) return;
    const int b = idx / NH, j = idx - (idx / NH) * NH;
    const float c1 = a1[j], c2 = a2[j];
    const float va = __fmul_rn(V0F, d_ann[idx]);
    float* dst = d_curp + ((size_t)(j >> 3) * NRR + b) * 8 + (j & 7);
    float p1 = 0.f, p2 = 0.f;
    for (int t = 0; t < TT; t++) {
        const float s = __fadd_rn(__fadd_rn(__fmul_rn(c1, p1), __fmul_rn(c2, p2)), va);
        dst[(size_t)t * NB * 8] = s;
        p2 = p1; p1 = s;
    }
}

// ---- K45: fused layer-2 LIF + layer-3 IIR -> panel layout (MLP-8) ----------
__global__ void k45_lif2_cur3(const float* __restrict__ a1, const float* __restrict__ a2)
{
    const int idx = blockIdx.x * blockDim.x + threadIdx.x;
    if (idx >= NB * NH) return;
    const int b = idx / NH, j = idx - (idx / NH) * NH;
    const float c1 = a1[j], c2 = a2[j];
    float* dst = d_curp + ((size_t)(j >> 3) * NRR + b) * 8 + (j & 7);
    float v = 0.f, ns = 1.f, p1 = 0.f, p2 = 0.f;
    for (int t0 = 0; t0 < TT; t0 += 8) {
        float w[8];
#pragma unroll
        for (int u = 0; u < 8; u++)
            w[u] = d_w2[(size_t)(t0 + u) * NB * NH + idx];
#pragma unroll
        for (int u = 0; u < 8; u++) {
            v = __fadd_rn(__fmul_rn(__fmul_rn(SIGF, v), ns), w[u]);
            const bool s = (__fadd_rn(v, -1.0f) > 0.f);
            ns = s ? 0.f : 1.f;
            const float inp = s ? V0F : 0.f;
            const float c = __fadd_rn(__fadd_rn(__fmul_rn(c1, p1), __fmul_rn(c2, p2)), inp);
            dst[(size_t)(t0 + u) * NB * 8] = c;
            p2 = p1; p1 = c;
        }
    }
}

// ---- K6: w3 = cur3 @ W3^T + b3  (strict k-chain; panel A reads) -------------
__global__ void __launch_bounds__(640) k6_gemm3(const float* __restrict__ W3,
                                                const float* __restrict__ b3)
{
    __shared__ float W3s[NO * NH];   // 20 KB
    __shared__ float Cs[64][68];     // padded for float4 alignment
    const int tid = threadIdx.x;
    const int r0 = blockIdx.x * 64;
    for (int i = tid; i < NO * NH; i += 640) W3s[i] = W3[i];
    const int rr = tid / 10, o = tid - rr * 10;
    float acc = 0.f;
    for (int k0 = 0; k0 < NH; k0 += 64) {
        __syncthreads();
        for (int i = tid; i < 64 * 64; i += 640) {
            const int r = i >> 6, kq = i & 63, kg = k0 + kq;
            Cs[r][kq] = (kg < NH)
                ? d_curp[((size_t)(kg >> 3) * NRR + r0 + r) * 8 + (kg & 7)] : 0.f;
        }
        __syncthreads();
        const int kl = (NH - k0 < 64) ? (NH - k0) : 64;   // 64 or 52 (mult of 4)
        for (int k = 0; k < kl; k += 4) {
            const float4 c = *reinterpret_cast<const float4*>(&Cs[rr][k]);
            const float4 w = *reinterpret_cast<const float4*>(&W3s[o * NH + k0 + k]);
            acc = fmaf(c.x, w.x, acc);
            acc = fmaf(c.y, w.y, acc);
            acc = fmaf(c.z, w.z, acc);
            acc = fmaf(c.w, w.w, acc);
        }
    }
    d_w3[(size_t)(r0 + rr) * NO + o] = __fadd_rn(acc, b3[o]);
}

// ---- K7: layer-3 LIF scan -> output [B,10,T] --------------------------------
__global__ void k7_lif3(float* __restrict__ out)
{
    const int idx = blockIdx.x * blockDim.x + threadIdx.x;
    if (idx >= NB * NO) return;
    const int b = idx / NO, o = idx - b * NO;
    float v = 0.f, ns = 1.f;
    for (int t0 = 0; t0 < TT; t0 += 4) {
        float w[4];
#pragma unroll
        for (int u = 0; u < 4; u++)
            w[u] = d_w3[((size_t)(t0 + u) * NB + b) * NO + o];
#pragma unroll
        for (int u = 0; u < 4; u++) {
            v = __fadd_rn(__fmul_rn(__fmul_rn(SIGF, v), ns), w[u]);
            const bool s = (__fadd_rn(v, -1.0f) > 0.f);
            ns = s ? 0.f : 1.f;
            out[((size_t)b * NO + o) * TT + t0 + u] = s ? 1.f : 0.f;
        }
    }
}

// ---------------------------------------------------------------------------
extern "C" void kernel_launch(void* const* d_in, const int* in_sizes, int n_in,
                              void* d_out, int out_size)
{
    const float* inputs = (const float*)d_in[0];
    const float* W1     = (const float*)d_in[1];
    const float* b1     = (const float*)d_in[2];
    const float* a1_2   = (const float*)d_in[3];
    const float* a2_2   = (const float*)d_in[4];
    const float* W2     = (const float*)d_in[5];
    const float* b2     = (const float*)d_in[6];
    const float* a1_3   = (const float*)d_in[7];
    const float* a2_3   = (const float*)d_in[8];
    const float* W3     = (const float*)d_in[9];
    const float* b3     = (const float*)d_in[10];

    float* ann;  cudaGetSymbolAddress((void**)&ann,  d_ann);
    float* curp; cudaGetSymbolAddress((void**)&curp, d_curp);
    float* w2;   cudaGetSymbolAddress((void**)&w2,   d_w2);

    // K1: ann = logistic(inputs @ W1^T + b1)  (M=256, K=784) — 128 CTAs
    gemm_k1<<<dim3(16, NB / 32), 256>>>(inputs, W1, b1, ann, NB, NH, NI);
    // K2: cur2 for all t (panel layout)
    k2_cur2<<<(NB * NH + 255) / 256, 256>>>(a1_2, a2_2);
    // dummy (keeps K3 at the ncu-captured launch slot)
    k_dummy<<<1, 1>>>();
    // K3: w2 = cur2_all @ W2^T + b2           (M=51200, K=500)
    gemm_strict_v9<<<dim3(8, NRR / 256), 256>>>(curp, W2, b2, w2, NRR, NH, NH);
    // K45: layer-2 LIF + layer-3 synapse IIR (fused, panel writes)
    k45_lif2_cur3<<<(NB * NH + 255) / 256, 256>>>(a1_3, a2_3);
    // K6: w3 = cur3_all @ W3^T + b3
    k6_gemm3<<<NRR / 64, 640>>>(W3, b3);
    // K7: layer-3 LIF -> output
    k7_lif3<<<(NB * NO + 255) / 256, 256>>>((float*)d_out);
}

// round 14
// speedup vs baseline: 1.3623x; 1.0531x over previous
#include <cuda_runtime.h>

#define NB 256
#define NH 500
#define NI 784
#define NO 10
#define TT 200
#define NRR (TT*NB)          // 51200 rows
#define NP2 64               // k-panels (8 wide), padded to 512 k

#define V0F  2.1165347359575993f   // f32(eta^(eta/(eta-1))/(eta-1)), eta=4
#define SIGF 0.7788007830714049f   // f32(exp(-1/4))

typedef unsigned long long u64;

// static device scratch (zero-initialized; pad panel 63 stays 0)
__device__ float d_ann[NB*NH];
__device__ float d_curp[(size_t)NP2*NRR*8]; // 104.9 MB, 8-k panel layout
__device__ float d_w2[(size_t)TT*NB*NH];    // 102.4 MB
__device__ float d_w3[TT*NB*NO];            // 2 MB

__device__ __forceinline__ void ffma2(u64 &acc, u64 a, u64 b) {
    asm("fma.rn.f32x2 %0, %1, %2, %0;" : "+l"(acc) : "l"(a), "l"(b));
}
__device__ __forceinline__ float2 unpack2(u64 v) {
    float2 f; asm("mov.b64 {%0,%1}, %2;" : "=f"(f.x), "=f"(f.y) : "l"(v));
    return f;
}
__device__ __forceinline__ u64 swap2(u64 v) {
    float2 f = unpack2(v);
    u64 s; asm("mov.b64 %0, {%1, %2};" : "=l"(s) : "f"(f.y), "f"(f.x));
    return s;
}

// XLA f32 tanh (rational approx, strict unfused) + logistic expansion
__device__ __forceinline__ float xla_tanh(float x) {
    const float xc = fminf(fmaxf(x, -7.90531110763549805f), 7.90531110763549805f);
    const float x2 = __fmul_rn(xc, xc);
    float p = -2.76076847742355e-16f;
    p = __fadd_rn(__fmul_rn(p, x2),  2.00018790482477e-13f);
    p = __fadd_rn(__fmul_rn(p, x2), -8.60467152213735e-11f);
    p = __fadd_rn(__fmul_rn(p, x2),  5.12229709037114e-08f);
    p = __fadd_rn(__fmul_rn(p, x2),  1.48572235717979e-05f);
    p = __fadd_rn(__fmul_rn(p, x2),  6.37261928875436e-04f);
    p = __fadd_rn(__fmul_rn(p, x2),  4.89352455891786e-03f);
    const float num = __fmul_rn(xc, p);
    float q = 1.19825839466702e-06f;
    q = __fadd_rn(__fmul_rn(q, x2), 1.18534705686654e-04f);
    q = __fadd_rn(__fmul_rn(q, x2), 2.26843463243900e-03f);
    q = __fadd_rn(__fmul_rn(q, x2), 4.89352518554385e-03f);
    const float t = __fdiv_rn(num, q);
    return (fabsf(x) < 0.0004f) ? x : t;
}
__device__ __forceinline__ float xla_logistic(float z) {
    return __fadd_rn(0.5f, __fmul_rn(0.5f, xla_tanh(__fmul_rn(0.5f, z))));
}

// ---------------------------------------------------------------------------
// Strict GEMM v10: w2[m,n] = chain_k fma(cur[m,k], W2[n,k]) + b2[n]
// = v9 diagonal-pair core with BK=16 (half the barriers). Dynamic smem
// (62.5 KB/CTA), 2 CTA/SM. Tile 256m x 64n x 16k, 256 threads.
// accD=(C[m][n],C[m+1][n+1]) <- a_pair*b_pair;
// accX=(C[m][n+1],C[m+1][n]) <- a_pair*swap(b_pair). 1.0 smem-B/FMA.
// Per output element: single accumulator, strictly k-ascending fma.rn chain.
// k 500..511 are exact identities (zero A panel + zero-filled B smem).
// ---------------------------------------------------------------------------
#define AS_STRIDE 388   // 32 chunks x (8 + 4 pad)
#define BS_STRIDE 100   // 8 chunks x (8 + 4 pad)
#define SMEM_V10_BYTES ((2*16*AS_STRIDE + 2*16*BS_STRIDE) * 4)

__global__ void __launch_bounds__(256, 2) gemm_strict_v10(
    const float* __restrict__ Ap,   // panels [NP2][M][8]
    const float* __restrict__ B,    // [N][K] row-major
    const float* __restrict__ bias, float* __restrict__ C,
    int M, int N, int K)
{
    extern __shared__ float smem[];
    float* AsBase = smem;                      // [2][16][AS_STRIDE]
    float* BsBase = smem + 2 * 16 * AS_STRIDE; // [2][16][BS_STRIDE]
#define AS(buf, k) (AsBase + ((buf) * 16 + (k)) * AS_STRIDE)
#define BS(buf, k) (BsBase + ((buf) * 16 + (k)) * BS_STRIDE)

    const int tid = threadIdx.x;
    const int tx  = tid & 7;           // n group: 8 n each
    const int ty  = tid >> 3;          // m chunk: 8 m each (0..31)
    const int m0  = blockIdx.y * 256;
    const int j0  = blockIdx.x * 64;

    const int bLr = tid >> 2;          // 0..63
    const int bLc = (tid & 3) * 4;     // {0,4,8,12}
    const bool bok = (j0 + bLr) < N;
    const int aSoff = (tid >> 3) * 12 + (tid & 7);   // natural slot
    const int bSoff = (bLr >> 3) * 12 + (bLr & 7);
    const int nblk = (K + 15) >> 4;    // 32

    u64 accD[4][4], accX[4][4];
#pragma unroll
    for (int i = 0; i < 4; i++)
#pragma unroll
        for (int j = 0; j < 4; j++) { accD[i][j] = 0ull; accX[i][j] = 0ull; }

    float4 ra0, ra1, ra2, ra3, rb;

    auto LD = [&](int blk) {
        const float4* s0 = reinterpret_cast<const float4*>(
            Ap + ((size_t)(2 * blk) * M + m0 + tid) * 8);
        ra0 = s0[0]; ra1 = s0[1];
        const float4* s1 = reinterpret_cast<const float4*>(
            Ap + ((size_t)(2 * blk + 1) * M + m0 + tid) * 8);
        ra2 = s1[0]; ra3 = s1[1];
        const int kgb = blk * 16 + bLc;
        rb = (kgb < K && bok) ? *reinterpret_cast<const float4*>(&B[(size_t)(j0 + bLr) * K + kgb])
                              : make_float4(0.f, 0.f, 0.f, 0.f);
    };
    auto ST = [&](int buf) {
        AS(buf, 0)[aSoff]  = ra0.x;  AS(buf, 1)[aSoff]  = ra0.y;
        AS(buf, 2)[aSoff]  = ra0.z;  AS(buf, 3)[aSoff]  = ra0.w;
        AS(buf, 4)[aSoff]  = ra1.x;  AS(buf, 5)[aSoff]  = ra1.y;
        AS(buf, 6)[aSoff]  = ra1.z;  AS(buf, 7)[aSoff]  = ra1.w;
        AS(buf, 8)[aSoff]  = ra2.x;  AS(buf, 9)[aSoff]  = ra2.y;
        AS(buf, 10)[aSoff] = ra2.z;  AS(buf, 11)[aSoff] = ra2.w;
        AS(buf, 12)[aSoff] = ra3.x;  AS(buf, 13)[aSoff] = ra3.y;
        AS(buf, 14)[aSoff] = ra3.z;  AS(buf, 15)[aSoff] = ra3.w;
        BS(buf, bLc + 0)[bSoff] = rb.x;
        BS(buf, bLc + 1)[bSoff] = rb.y;
        BS(buf, bLc + 2)[bSoff] = rb.z;
        BS(buf, bLc + 3)[bSoff] = rb.w;
    };

    LD(0); ST(0); __syncthreads();

    for (int blk = 0; blk < nblk; blk++) {
        const int buf = blk & 1;
        if (blk + 1 < nblk) LD(blk + 1);
#pragma unroll
        for (int k = 0; k < 16; k++) {
            const float* as = AS(buf, k);
            const float* bs_ = BS(buf, k);
            const ulonglong2 a01 = *reinterpret_cast<const ulonglong2*>(&as[ty * 12]);
            const ulonglong2 a23 = *reinterpret_cast<const ulonglong2*>(&as[ty * 12 + 4]);
            const u64 a[4] = {a01.x, a01.y, a23.x, a23.y};
            const ulonglong2 b01 = *reinterpret_cast<const ulonglong2*>(&bs_[tx * 12]);
            const ulonglong2 b23 = *reinterpret_cast<const ulonglong2*>(&bs_[tx * 12 + 4]);
            const u64 b[4]  = {b01.x, b01.y, b23.x, b23.y};
            const u64 bw[4] = {swap2(b[0]), swap2(b[1]), swap2(b[2]), swap2(b[3])};
#pragma unroll
            for (int mi = 0; mi < 4; mi++)
#pragma unroll
                for (int nj = 0; nj < 4; nj++) {
                    ffma2(accD[mi][nj], a[mi], b[nj]);
                    ffma2(accX[mi][nj], a[mi], bw[nj]);
                }
        }
        if (blk + 1 < nblk) ST(buf ^ 1);
        __syncthreads();
    }

#pragma unroll
    for (int mi = 0; mi < 4; mi++) {
        const int m = m0 + ty * 8 + 2 * mi;
#pragma unroll
        for (int nj = 0; nj < 4; nj++) {
            const int n = j0 + tx * 8 + 2 * nj;
            const float2 D = unpack2(accD[mi][nj]);
            const float2 X = unpack2(accX[mi][nj]);
            if (n < N) {
                const float bn = bias[n];
                C[(size_t)m * N + n]       = __fadd_rn(D.x, bn);
                C[(size_t)(m + 1) * N + n] = __fadd_rn(X.y, bn);
            }
            if (n + 1 < N) {
                const float bn1 = bias[n + 1];
                C[(size_t)m * N + n + 1]       = __fadd_rn(X.x, bn1);
                C[(size_t)(m + 1) * N + n + 1] = __fadd_rn(D.y, bn1);
            }
        }
    }
#undef AS
#undef BS
}

// ---------------------------------------------------------------------------
// K1 GEMM: 32m x 32n x 16k tiles, 256 threads, 2m x 2n per thread. 128 CTAs.
// ---------------------------------------------------------------------------
__global__ void __launch_bounds__(256) gemm_k1(
    const float* __restrict__ A, const float* __restrict__ B,
    const float* __restrict__ bias, float* __restrict__ C,
    int M, int N, int K)
{
    __shared__ float As[2][16][36];
    __shared__ float Bs[2][16][36];

    const int tid = threadIdx.x;
    const int tx  = tid & 15;
    const int ty  = tid >> 4;
    const int m0  = blockIdx.y * 32;
    const int j0  = blockIdx.x * 32;

    const int lr = tid >> 3;          // 0..31
    const int lc = (tid & 7) * 2;     // 0..14
    const bool bok = (j0 + lr) < N;
    const int nblk = K / 16;

    float acc[2][2] = {{0.f, 0.f}, {0.f, 0.f}};
    float2 ra, rb;

    auto LD = [&](int blk) {
        const int kg = blk * 16 + lc;
        ra = *reinterpret_cast<const float2*>(&A[(size_t)(m0 + lr) * K + kg]);
        rb = bok ? *reinterpret_cast<const float2*>(&B[(size_t)(j0 + lr) * K + kg])
                 : make_float2(0.f, 0.f);
    };
    auto ST = [&](int buf) {
        As[buf][lc + 0][lr] = ra.x;  As[buf][lc + 1][lr] = ra.y;
        Bs[buf][lc + 0][lr] = rb.x;  Bs[buf][lc + 1][lr] = rb.y;
    };

    LD(0); ST(0); __syncthreads();

    for (int blk = 0; blk < nblk; blk++) {
        const int buf = blk & 1;
        if (blk + 1 < nblk) LD(blk + 1);
#pragma unroll
        for (int k = 0; k < 16; k++) {
            const float a0 = As[buf][k][ty * 2], a1 = As[buf][k][ty * 2 + 1];
            const float b0 = Bs[buf][k][tx * 2], b1 = Bs[buf][k][tx * 2 + 1];
            acc[0][0] = fmaf(a0, b0, acc[0][0]);
            acc[0][1] = fmaf(a0, b1, acc[0][1]);
            acc[1][0] = fmaf(a1, b0, acc[1][0]);
            acc[1][1] = fmaf(a1, b1, acc[1][1]);
        }
        if (blk + 1 < nblk) ST(buf ^ 1);
        __syncthreads();
    }

#pragma unroll
    for (int i = 0; i < 2; i++) {
        const int m = m0 + ty * 2 + i;
#pragma unroll
        for (int j = 0; j < 2; j++) {
            const int n = j0 + tx * 2 + j;
            if (n < N)
                C[(size_t)m * N + n] = xla_logistic(__fadd_rn(acc[i][j], bias[n]));
        }
    }
}

// ---- dummy: keeps K3 at the ncu-captured launch slot ------------------------
__global__ void k_dummy() {}

// ---- K2: cur2(t) for all t -> panel layout (strict rounding) ----------------
__global__ void k2_cur2(const float* __restrict__ a1, const float* __restrict__ a2)
{
    const int idx = blockIdx.x * blockDim.x + threadIdx.x;
    if (idx >= NB * NH) return;
    const int b = idx / NH, j = idx - (idx / NH) * NH;
    const float c1 = a1[j], c2 = a2[j];
    const float va = __fmul_rn(V0F, d_ann[idx]);
    float* dst = d_curp + ((size_t)(j >> 3) * NRR + b) * 8 + (j & 7);
    float p1 = 0.f, p2 = 0.f;
    for (int t = 0; t < TT; t++) {
        const float s = __fadd_rn(__fadd_rn(__fmul_rn(c1, p1), __fmul_rn(c2, p2)), va);
        dst[(size_t)t * NB * 8] = s;
        p2 = p1; p1 = s;
    }
}

// ---- K45: fused layer-2 LIF + layer-3 IIR -> panel layout (MLP-8) ----------
__global__ void k45_lif2_cur3(const float* __restrict__ a1, const float* __restrict__ a2)
{
    const int idx = blockIdx.x * blockDim.x + threadIdx.x;
    if (idx >= NB * NH) return;
    const int b = idx / NH, j = idx - (idx / NH) * NH;
    const float c1 = a1[j], c2 = a2[j];
    float* dst = d_curp + ((size_t)(j >> 3) * NRR + b) * 8 + (j & 7);
    float v = 0.f, ns = 1.f, p1 = 0.f, p2 = 0.f;
    for (int t0 = 0; t0 < TT; t0 += 8) {
        float w[8];
#pragma unroll
        for (int u = 0; u < 8; u++)
            w[u] = d_w2[(size_t)(t0 + u) * NB * NH + idx];
#pragma unroll
        for (int u = 0; u < 8; u++) {
            v = __fadd_rn(__fmul_rn(__fmul_rn(SIGF, v), ns), w[u]);
            const bool s = (__fadd_rn(v, -1.0f) > 0.f);
            ns = s ? 0.f : 1.f;
            const float inp = s ? V0F : 0.f;
            const float c = __fadd_rn(__fadd_rn(__fmul_rn(c1, p1), __fmul_rn(c2, p2)), inp);
            dst[(size_t)(t0 + u) * NB * 8] = c;
            p2 = p1; p1 = c;
        }
    }
}

// ---- K6: w3 = cur3 @ W3^T + b3  (strict k-chain; panel A reads) -------------
__global__ void __launch_bounds__(640) k6_gemm3(const float* __restrict__ W3,
                                                const float* __restrict__ b3)
{
    __shared__ float W3s[NO * NH];   // 20 KB
    __shared__ float Cs[64][68];     // padded for float4 alignment
    const int tid = threadIdx.x;
    const int r0 = blockIdx.x * 64;
    for (int i = tid; i < NO * NH; i += 640) W3s[i] = W3[i];
    const int rr = tid / 10, o = tid - rr * 10;
    float acc = 0.f;
    for (int k0 = 0; k0 < NH; k0 += 64) {
        __syncthreads();
        for (int i = tid; i < 64 * 64; i += 640) {
            const int r = i >> 6, kq = i & 63, kg = k0 + kq;
            Cs[r][kq] = (kg < NH)
                ? d_curp[((size_t)(kg >> 3) * NRR + r0 + r) * 8 + (kg & 7)] : 0.f;
        }
        __syncthreads();
        const int kl = (NH - k0 < 64) ? (NH - k0) : 64;   // 64 or 52 (mult of 4)
        for (int k = 0; k < kl; k += 4) {
            const float4 c = *reinterpret_cast<const float4*>(&Cs[rr][k]);
            const float4 w = *reinterpret_cast<const float4*>(&W3s[o * NH + k0 + k]);
            acc = fmaf(c.x, w.x, acc);
            acc = fmaf(c.y, w.y, acc);
            acc = fmaf(c.z, w.z, acc);
            acc = fmaf(c.w, w.w, acc);
        }
    }
    d_w3[(size_t)(r0 + rr) * NO + o] = __fadd_rn(acc, b3[o]);
}

// ---- K7: layer-3 LIF scan -> output [B,10,T] --------------------------------
__global__ void k7_lif3(float* __restrict__ out)
{
    const int idx = blockIdx.x * blockDim.x + threadIdx.x;
    if (idx >= NB * NO) return;
    const int b = idx / NO, o = idx - b * NO;
    float v = 0.f, ns = 1.f;
    for (int t0 = 0; t0 < TT; t0 += 4) {
        float w[4];
#pragma unroll
        for (int u = 0; u < 4; u++)
            w[u] = d_w3[((size_t)(t0 + u) * NB + b) * NO + o];
#pragma unroll
        for (int u = 0; u < 4; u++) {
            v = __fadd_rn(__fmul_rn(__fmul_rn(SIGF, v), ns), w[u]);
            const bool s = (__fadd_rn(v, -1.0f) > 0.f);
            ns = s ? 0.f : 1.f;
            out[((size_t)b * NO + o) * TT + t0 + u] = s ? 1.f : 0.f;
        }
    }
}

// ---------------------------------------------------------------------------
extern "C" void kernel_launch(void* const* d_in, const int* in_sizes, int n_in,
                              void* d_out, int out_size)
{
    const float* inputs = (const float*)d_in[0];
    const float* W1     = (const float*)d_in[1];
    const float* b1     = (const float*)d_in[2];
    const float* a1_2   = (const float*)d_in[3];
    const float* a2_2   = (const float*)d_in[4];
    const float* W2     = (const float*)d_in[5];
    const float* b2     = (const float*)d_in[6];
    const float* a1_3   = (const float*)d_in[7];
    const float* a2_3   = (const float*)d_in[8];
    const float* W3     = (const float*)d_in[9];
    const float* b3     = (const float*)d_in[10];

    float* ann;  cudaGetSymbolAddress((void**)&ann,  d_ann);
    float* curp; cudaGetSymbolAddress((void**)&curp, d_curp);
    float* w2;   cudaGetSymbolAddress((void**)&w2,   d_w2);

    cudaFuncSetAttribute(gemm_strict_v10,
                         cudaFuncAttributeMaxDynamicSharedMemorySize,
                         SMEM_V10_BYTES);

    // K1: ann = logistic(inputs @ W1^T + b1)  (M=256, K=784) — 128 CTAs
    gemm_k1<<<dim3(16, NB / 32), 256>>>(inputs, W1, b1, ann, NB, NH, NI);
    // K2: cur2 for all t (panel layout)
    k2_cur2<<<(NB * NH + 255) / 256, 256>>>(a1_2, a2_2);
    // dummy (keeps K3 at the ncu-captured launch slot)
    k_dummy<<<1, 1>>>();
    // K3: w2 = cur2_all @ W2^T + b2           (M=51200, K=500)
    gemm_strict_v10<<<dim3(8, NRR / 256), 256, SMEM_V10_BYTES>>>(
        curp, W2, b2, w2, NRR, NH, NH);
    // K45: layer-2 LIF + layer-3 synapse IIR (fused, panel writes)
    k45_lif2_cur3<<<(NB * NH + 255) / 256, 256>>>(a1_3, a2_3);
    // K6: w3 = cur3_all @ W3^T + b3
    k6_gemm3<<<NRR / 64, 640>>>(W3, b3);
    // K7: layer-3 LIF -> output
    k7_lif3<<<(NB * NO + 255) / 256, 256>>>((float*)d_out);
}